// round 6
// baseline (speedup 1.0000x reference)
#include <cuda_runtime.h>
#include <cuda_bf16.h>
#include <cstdint>

#define BATCH 1024
#define NN    8192
#define NB    8
#define TOTAL_IN 512

// Fragment-order scratch (bf16), filled by prep kernel.
__device__ uint4 g_xfrag[64 * 32 * 32];     // 1 MB
__device__ uint4 g_wfrag2[1024 * 16 * 32];  // 8 MB

__device__ __forceinline__ uint32_t pack_bf2(float lo, float hi) {
    __nv_bfloat162 h = __floats2bfloat162_rn(lo, hi);
    return *reinterpret_cast<uint32_t*>(&h);
}

// ---------------- prep: permute into mma fragment order ----------------
__global__ __launch_bounds__(256)
void prep_kernel(const float* __restrict__ x, const float* __restrict__ w) {
    const int NXF  = 64 * 32 * 32;
    const int NWF2 = 1024 * 16 * 32;
    int i = blockIdx.x * blockDim.x + threadIdx.x;
    if (i < NXF) {
        int lane = i & 31, ks = (i >> 5) & 31, mt = i >> 10;
        int k = ks >> 2, s = ks & 3, g = lane >> 2, q = lane & 3;
        int kk = k * 64 + s * 16;
        const float* xr0 = x + (size_t)(mt * 16 + g) * TOTAL_IN + kk + 2 * q;
        const float* xr1 = xr0 + 8 * TOTAL_IN;
        float2 v00 = *(const float2*)xr0;
        float2 v10 = *(const float2*)xr1;
        float2 v01 = *(const float2*)(xr0 + 8);
        float2 v11 = *(const float2*)(xr1 + 8);
        uint4 o;
        o.x = pack_bf2(v00.x, v00.y);
        o.y = pack_bf2(v10.x, v10.y);
        o.z = pack_bf2(v01.x, v01.y);
        o.w = pack_bf2(v11.x, v11.y);
        g_xfrag[i] = o;
    } else if (i - NXF < NWF2) {
        int j = i - NXF;
        int lane = j & 31, t = (j >> 5) & 15, nt = j >> 9;
        int g = lane >> 2, q = lane & 3;
        int k = t >> 1;
        int s0 = (2 * t) & 3;
        int kk = k * 64 + s0 * 16;
        const float* wr = w + (size_t)(nt * 8 + g) * TOTAL_IN + kk + 2 * q;
        float2 e0 = *(const float2*)wr;
        float2 e1 = *(const float2*)(wr + 8);
        float2 o0 = *(const float2*)(wr + 16);
        float2 o1 = *(const float2*)(wr + 24);
        uint4 o;
        o.x = pack_bf2(fmaxf(e0.x, 0.f), fmaxf(e0.y, 0.f));
        o.y = pack_bf2(fmaxf(e1.x, 0.f), fmaxf(e1.y, 0.f));
        o.z = pack_bf2(fmaxf(o0.x, 0.f), fmaxf(o0.y, 0.f));
        o.w = pack_bf2(fmaxf(o1.x, 0.f), fmaxf(o1.y, 0.f));
        g_wfrag2[j] = o;
    }
}

__device__ __forceinline__ void mma_bf16(float acc[4], const uint4& a,
                                         uint32_t b0, uint32_t b1) {
    asm volatile(
        "mma.sync.aligned.m16n8k16.row.col.f32.bf16.bf16.f32 "
        "{%0,%1,%2,%3}, {%4,%5,%6,%7}, {%8,%9}, {%0,%1,%2,%3};"
        : "+f"(acc[0]), "+f"(acc[1]), "+f"(acc[2]), "+f"(acc[3])
        : "r"(a.x), "r"(a.y), "r"(a.z), "r"(a.w), "r"(b0), "r"(b1));
}

__device__ __forceinline__ uint32_t smem_u32(const void* p) {
    uint32_t a;
    asm("{ .reg .u64 t; cvta.to.shared.u64 t, %1; cvt.u32.u64 %0, t; }" : "=r"(a) : "l"(p));
    return a;
}

__device__ __forceinline__ void cp16(uint32_t dst, const void* src) {
    asm volatile("cp.async.cg.shared.global [%0], [%1], 16;" :: "r"(dst), "l"(src));
}

// ---------------- main fused kernel ----------------
// CTA: 256 threads / 8 warps. Tile M=16 (batch) x N=64 (neurons).
// grid = (8192/64, 1024/16) = (128, 64)
// smem (floats): GS[16][64][8] @0, PL @8192, GE[16][64] @16384, VM @17408; 73728 B
#define GS_F 0
#define PL_F 8192
#define GE_F 16384
#define VM_F 17408
#define SMEM_BYTES 73728

__global__ __launch_bounds__(256, 3)
void dendrite_main(const float* __restrict__ g_syn,
                   const float* __restrict__ plateaus,
                   const float* __restrict__ g_e,
                   const float* __restrict__ v_mem,
                   float* __restrict__ out)
{
    const float SYN_DECAY     = 0.99335550625f;  // exp(-0.1/15)
    const float PLATEAU_DECAY = 0.99875078085f;  // exp(-0.1/80)
    const float E_DECAY       = 0.98019867331f;  // exp(-0.1/5)

    extern __shared__ float smf[];

    const int tid = threadIdx.x;
    const int w = tid >> 5, lane = tid & 31;
    const int mt = blockIdx.y;
    const int bx = blockIdx.x;
    const int nt8 = bx * 8 + w;
    const int b0 = mt * 16, n0 = bx * 64;

    // ---- prologue: async-prefetch the whole state tile (72 KB) ----
    {
        const uint32_t sgs = smem_u32(&smf[GS_F]);
        const uint32_t spl = smem_u32(&smf[PL_F]);
        // g_syn / plateaus: 16 rows x 2 KB = 2048 x 16B chunks each
        #pragma unroll
        for (int i = 0; i < 8; i++) {
            const int c = tid + i * 256;
            const int bl = c >> 7, o = c & 127;     // o: 16B chunk within row
            const size_t goff = ((size_t)(b0 + bl) * NN + n0) * NB + o * 4;
            cp16(sgs + c * 16, g_syn + goff);
            cp16(spl + c * 16, plateaus + goff);
        }
        // g_e / v_mem: 16 rows x 256B = 256 x 16B chunks each
        {
            const int bl = tid >> 4, o = tid & 15;
            const size_t goff = (size_t)(b0 + bl) * NN + n0 + o * 4;
            cp16(smem_u32(&smf[GE_F]) + tid * 16, g_e + goff);
            cp16(smem_u32(&smf[VM_F]) + tid * 16, v_mem + goff);
        }
        asm volatile("cp.async.commit_group;" ::: "memory");
    }

    // ---- MMA mainloop (overlapped with the async state stream) ----
    const uint4* xf  = g_xfrag  + (size_t)mt  * 1024 + lane;
    const uint4* wf2 = g_wfrag2 + (size_t)nt8 * 512  + lane;

    float acc[NB][4];
    #pragma unroll
    for (int k = 0; k < NB; k++)
        #pragma unroll
        for (int j = 0; j < 4; j++) acc[k][j] = 0.f;

    #pragma unroll
    for (int t = 0; t < 16; t++) {
        uint4 a0 = xf[(2 * t) * 32];
        uint4 a1 = xf[(2 * t + 1) * 32];
        uint4 bb = wf2[t * 32];
        mma_bf16(acc[t >> 1], a0, bb.x, bb.y);
        mma_bf16(acc[t >> 1], a1, bb.z, bb.w);
    }

    // ---- wait for state tile, then fused epilogue from smem ----
    asm volatile("cp.async.wait_group 0;" ::: "memory");
    __syncthreads();

    const int g = lane >> 2, q = lane & 3;
    #pragma unroll
    for (int h = 0; h < 2; h++) {
        #pragma unroll
        for (int j = 0; j < 2; j++) {
            const int bl = g + h * 8;
            const int nl = w * 8 + 2 * q + j;
            const int p  = bl * 64 + nl;            // pair index in tile

            const float4* gp = (const float4*)&smf[GS_F + p * 8];
            const float4* pp = (const float4*)&smf[PL_F + p * 8];
            float4 gsA = gp[0], gsB = gp[1];
            float4 plA = pp[0], plB = pp[1];
            const float gev0 = smf[GE_F + p];
            const float vm0  = smf[VM_F + p];

            float gs[8] = {gsA.x, gsA.y, gsA.z, gsA.w, gsB.x, gsB.y, gsB.z, gsB.w};
            float pl[8] = {plA.x, plA.y, plA.z, plA.w, plB.x, plB.y, plB.z, plB.w};

            float soma = 0.f;
            #pragma unroll
            for (int k = 0; k < NB; k++) {
                const float gv = fmaf(SYN_DECAY, gs[k], acc[k][2 * h + j]);
                const bool supra = gv > 0.3f;
                const float nmda = gv * (supra ? 3.0f : 0.8f);
                float pv = PLATEAU_DECAY * pl[k];
                if (supra) pv = fmaxf(pv, nmda);
                // 2*tanh(t/2) = 2*(1-e^-t)/(1+e^-t)
                const float e = __expf(-(nmda + pv));
                soma += 2.0f * __fdividef(1.0f - e, 1.0f + e);
            }
            const float ge_n = fmaf(E_DECAY, gev0, soma);
            float v = vm0 + 0.005f * (ge_n * (3.0f - vm0) - vm0);
            const float spk = (v >= 1.0f) ? 1.0f : 0.0f;
            if (v >= 1.0f) v = 0.0f;

            const size_t idx = (size_t)(b0 + bl) * NN + n0 + nl;
            out[idx] = spk;
            out[(size_t)BATCH * NN + idx] = v;
        }
    }
}

extern "C" void kernel_launch(void* const* d_in, const int* in_sizes, int n_in,
                              void* d_out, int out_size) {
    const float* inputs   = (const float*)d_in[0];
    const float* bw       = (const float*)d_in[1];
    const float* g_syn    = (const float*)d_in[2];
    const float* plateaus = (const float*)d_in[3];
    const float* g_e      = (const float*)d_in[4];
    const float* v_mem    = (const float*)d_in[5];
    float* out = (float*)d_out;

    cudaFuncSetAttribute(dendrite_main,
                         cudaFuncAttributeMaxDynamicSharedMemorySize, SMEM_BYTES);

    const int NTOT = 64 * 32 * 32 + 1024 * 16 * 32;
    prep_kernel<<<(NTOT + 255) / 256, 256>>>(inputs, bw);

    dim3 grid(NN / 64, BATCH / 16);   // (128, 64)
    dendrite_main<<<grid, 256, SMEM_BYTES>>>(g_syn, plateaus, g_e, v_mem, out);
}

// round 8
// speedup vs baseline: 1.1010x; 1.1010x over previous
#include <cuda_runtime.h>
#include <cuda_bf16.h>
#include <cstdint>

#define BATCH 1024
#define NN    8192
#define NB    8
#define TOTAL_IN 512

// Fragment-order scratch (bf16), filled by prep kernel.
// xfrag : [64 mtiles][32 ks][32 lanes] uint4 (a0..a3)                 = 1 MB
// wfrag2: [1024 ntiles][16 t][32 lanes] uint4 (b0e,b1e,b0o,b1o)       = 8 MB
__device__ uint4 g_xfrag[64 * 32 * 32];
__device__ uint4 g_wfrag2[1024 * 16 * 32];

__device__ __forceinline__ uint32_t pack_bf2(float lo, float hi) {
    __nv_bfloat162 h = __floats2bfloat162_rn(lo, hi);
    return *reinterpret_cast<uint32_t*>(&h);
}

// ---------------- prep: permute into mma fragment order ----------------
__global__ __launch_bounds__(256)
void prep_kernel(const float* __restrict__ x, const float* __restrict__ w) {
    const int NXF  = 64 * 32 * 32;
    const int NWF2 = 1024 * 16 * 32;
    int i = blockIdx.x * blockDim.x + threadIdx.x;
    if (i < NXF) {
        int lane = i & 31, ks = (i >> 5) & 31, mt = i >> 10;
        int k = ks >> 2, s = ks & 3, g = lane >> 2, q = lane & 3;
        int kk = k * 64 + s * 16;
        const float* xr0 = x + (size_t)(mt * 16 + g) * TOTAL_IN + kk + 2 * q;
        const float* xr1 = xr0 + 8 * TOTAL_IN;
        float2 v00 = *(const float2*)xr0;
        float2 v10 = *(const float2*)xr1;
        float2 v01 = *(const float2*)(xr0 + 8);
        float2 v11 = *(const float2*)(xr1 + 8);
        uint4 o;
        o.x = pack_bf2(v00.x, v00.y);   // a0: (g,   2q..2q+1)
        o.y = pack_bf2(v10.x, v10.y);   // a1: (g+8, ...)
        o.z = pack_bf2(v01.x, v01.y);   // a2: (g,   2q+8..)
        o.w = pack_bf2(v11.x, v11.y);   // a3: (g+8, 2q+8..)
        g_xfrag[i] = o;
    } else if (i - NXF < NWF2) {
        int j = i - NXF;
        int lane = j & 31, t = (j >> 5) & 15, nt = j >> 9;
        int g = lane >> 2, q = lane & 3;
        int k = t >> 1;
        int s0 = (2 * t) & 3;
        int kk = k * 64 + s0 * 16;
        const float* wr = w + (size_t)(nt * 8 + g) * TOTAL_IN + kk + 2 * q;
        float2 e0 = *(const float2*)wr;          // even ks, b0
        float2 e1 = *(const float2*)(wr + 8);    // even ks, b1
        float2 o0 = *(const float2*)(wr + 16);   // odd  ks, b0
        float2 o1 = *(const float2*)(wr + 24);   // odd  ks, b1
        uint4 o;
        o.x = pack_bf2(fmaxf(e0.x, 0.f), fmaxf(e0.y, 0.f));
        o.y = pack_bf2(fmaxf(e1.x, 0.f), fmaxf(e1.y, 0.f));
        o.z = pack_bf2(fmaxf(o0.x, 0.f), fmaxf(o0.y, 0.f));
        o.w = pack_bf2(fmaxf(o1.x, 0.f), fmaxf(o1.y, 0.f));
        g_wfrag2[j] = o;
    }
}

__device__ __forceinline__ void mma_bf16(float acc[4], const uint4& a,
                                         uint32_t b0, uint32_t b1) {
    asm volatile(
        "mma.sync.aligned.m16n8k16.row.col.f32.bf16.bf16.f32 "
        "{%0,%1,%2,%3}, {%4,%5,%6,%7}, {%8,%9}, {%0,%1,%2,%3};"
        : "+f"(acc[0]), "+f"(acc[1]), "+f"(acc[2]), "+f"(acc[3])
        : "r"(a.x), "r"(a.y), "r"(a.z), "r"(a.w), "r"(b0), "r"(b1));
}

// ---------------- main fused kernel ----------------
// CTA: 128 threads / 4 warps. Warp tile M=16 x N=16 (two n8-tiles share a-frags).
// CTA tile: M=16 x N=64. grid = (8192/64, 1024/16) = (128, 64)
__global__ __launch_bounds__(128)
void dendrite_main(const float* __restrict__ g_syn,
                   const float* __restrict__ plateaus,
                   const float* __restrict__ g_e,
                   const float* __restrict__ v_mem,
                   float* __restrict__ out)
{
    const float SYN_DECAY     = 0.99335550625f;  // exp(-0.1/15)
    const float PLATEAU_DECAY = 0.99875078085f;  // exp(-0.1/80)
    const float E_DECAY       = 0.98019867331f;  // exp(-0.1/5)

    const int tid = threadIdx.x;
    const int w = tid >> 5, lane = tid & 31;
    const int mt = blockIdx.y;
    const int bx = blockIdx.x;
    const int b0 = mt * 16, n0 = bx * 64;

    const uint4* xf  = g_xfrag  + (size_t)mt * 1024 + lane;
    const uint4* wfA = g_wfrag2 + (size_t)(bx * 8 + 2 * w) * 512 + lane;
    const uint4* wfB = wfA + 512;

    float accA[NB][4], accB[NB][4];
    #pragma unroll
    for (int k = 0; k < NB; k++)
        #pragma unroll
        for (int j = 0; j < 4; j++) { accA[k][j] = 0.f; accB[k][j] = 0.f; }

    #pragma unroll
    for (int t = 0; t < 16; t++) {
        uint4 a0 = xf[(2 * t) * 32];
        uint4 a1 = xf[(2 * t + 1) * 32];
        uint4 bA = wfA[t * 32];
        uint4 bB = wfB[t * 32];
        const int k = t >> 1;
        mma_bf16(accA[k], a0, bA.x, bA.y);
        mma_bf16(accB[k], a0, bB.x, bB.y);
        mma_bf16(accA[k], a1, bA.z, bA.w);
        mma_bf16(accB[k], a1, bB.z, bB.w);
    }

    // ---- fused elementwise epilogue (round-3 mapping, per n8-tile) ----
    const int g = lane >> 2, q = lane & 3;

    #pragma unroll
    for (int nt = 0; nt < 2; nt++) {
        const int n = n0 + w * 16 + nt * 8 + 2 * q;   // this thread's 2 neuron cols
        #pragma unroll
        for (int h = 0; h < 2; h++) {
            const int b = b0 + g + h * 8;
            const size_t base = (size_t)b * NN + n;

            const float4* gp = (const float4*)(g_syn + base * NB);
            const float4* pp = (const float4*)(plateaus + base * NB);
            float4 gsA = gp[0], gsB = gp[1], gsC = gp[2], gsD = gp[3];
            float4 plA = pp[0], plB = pp[1], plC = pp[2], plD = pp[3];
            float2 ge2 = *(const float2*)(g_e + base);
            float2 vm2 = *(const float2*)(v_mem + base);

            float gs[2][8] = {{gsA.x, gsA.y, gsA.z, gsA.w, gsB.x, gsB.y, gsB.z, gsB.w},
                              {gsC.x, gsC.y, gsC.z, gsC.w, gsD.x, gsD.y, gsD.z, gsD.w}};
            float pl[2][8] = {{plA.x, plA.y, plA.z, plA.w, plB.x, plB.y, plB.z, plB.w},
                              {plC.x, plC.y, plC.z, plC.w, plD.x, plD.y, plD.z, plD.w}};
            float gev[2] = {ge2.x, ge2.y};
            float vmv[2] = {vm2.x, vm2.y};
            float spk[2], vo[2];

            #pragma unroll
            for (int j = 0; j < 2; j++) {
                float soma = 0.f;
                #pragma unroll
                for (int k = 0; k < NB; k++) {
                    const float av = nt ? accB[k][2 * h + j] : accA[k][2 * h + j];
                    const float gv = fmaf(SYN_DECAY, gs[j][k], av);
                    const bool supra = gv > 0.3f;
                    const float nmda = gv * (supra ? 3.0f : 0.8f);
                    float pv = PLATEAU_DECAY * pl[j][k];
                    if (supra) pv = fmaxf(pv, nmda);
                    // 2*tanh(t/2) = 2*(1-e^-t)/(1+e^-t)
                    const float e = __expf(-(nmda + pv));
                    soma += 2.0f * __fdividef(1.0f - e, 1.0f + e);
                }
                const float ge_n = fmaf(E_DECAY, gev[j], soma);
                float v = vmv[j] + 0.005f * (ge_n * (3.0f - vmv[j]) - vmv[j]);
                spk[j] = (v >= 1.0f) ? 1.0f : 0.0f;
                vo[j]  = (v >= 1.0f) ? 0.0f : v;
            }
            *(float2*)(out + base) = make_float2(spk[0], spk[1]);
            *(float2*)(out + (size_t)BATCH * NN + base) = make_float2(vo[0], vo[1]);
        }
    }
}

extern "C" void kernel_launch(void* const* d_in, const int* in_sizes, int n_in,
                              void* d_out, int out_size) {
    const float* inputs   = (const float*)d_in[0];
    const float* bw       = (const float*)d_in[1];
    const float* g_syn    = (const float*)d_in[2];
    const float* plateaus = (const float*)d_in[3];
    const float* g_e      = (const float*)d_in[4];
    const float* v_mem    = (const float*)d_in[5];
    float* out = (float*)d_out;

    const int NTOT = 64 * 32 * 32 + 1024 * 16 * 32;
    prep_kernel<<<(NTOT + 255) / 256, 256>>>(inputs, bw);

    dim3 grid(NN / 64, BATCH / 16);   // (128, 64) = 8192 CTAs of 128 threads
    dendrite_main<<<grid, 128>>>(g_syn, plateaus, g_e, v_mem, out);
}

// round 10
// speedup vs baseline: 1.1801x; 1.0719x over previous
#include <cuda_runtime.h>
#include <cuda_fp16.h>
#include <cstdint>

#define BATCH 1024
#define NN    8192
#define NB    8
#define TOTAL_IN 512

// Fragment-order scratch (fp16), filled by prep kernel.
// xfrag : [64 mtiles][32 ks][32 lanes] uint4 (a0..a3)                 = 1 MB
// wfrag2: [1024 ntiles][16 t][32 lanes] uint4 (b0e,b1e,b0o,b1o)       = 8 MB
__device__ uint4 g_xfrag[64 * 32 * 32];
__device__ uint4 g_wfrag2[1024 * 16 * 32];

__device__ __forceinline__ uint32_t pack_h2(float lo, float hi) {
    __half2 h = __floats2half2_rn(lo, hi);
    return *reinterpret_cast<uint32_t*>(&h);
}

// ---------------- prep: permute into mma fragment order (fp16) ----------------
__global__ __launch_bounds__(256)
void prep_kernel(const float* __restrict__ x, const float* __restrict__ w) {
    const int NXF  = 64 * 32 * 32;
    const int NWF2 = 1024 * 16 * 32;
    int i = blockIdx.x * blockDim.x + threadIdx.x;
    if (i < NXF) {
        int lane = i & 31, ks = (i >> 5) & 31, mt = i >> 10;
        int k = ks >> 2, s = ks & 3, g = lane >> 2, q = lane & 3;
        int kk = k * 64 + s * 16;
        const float* xr0 = x + (size_t)(mt * 16 + g) * TOTAL_IN + kk + 2 * q;
        const float* xr1 = xr0 + 8 * TOTAL_IN;
        float2 v00 = *(const float2*)xr0;
        float2 v10 = *(const float2*)xr1;
        float2 v01 = *(const float2*)(xr0 + 8);
        float2 v11 = *(const float2*)(xr1 + 8);
        uint4 o;
        o.x = pack_h2(v00.x, v00.y);   // a0: (g,   2q..2q+1)
        o.y = pack_h2(v10.x, v10.y);   // a1: (g+8, ...)
        o.z = pack_h2(v01.x, v01.y);   // a2: (g,   2q+8..)
        o.w = pack_h2(v11.x, v11.y);   // a3: (g+8, 2q+8..)
        g_xfrag[i] = o;
    } else if (i - NXF < NWF2) {
        int j = i - NXF;
        int lane = j & 31, t = (j >> 5) & 15, nt = j >> 9;
        int g = lane >> 2, q = lane & 3;
        int k = t >> 1;
        int s0 = (2 * t) & 3;
        int kk = k * 64 + s0 * 16;
        const float* wr = w + (size_t)(nt * 8 + g) * TOTAL_IN + kk + 2 * q;
        float2 e0 = *(const float2*)wr;          // even ks, b0
        float2 e1 = *(const float2*)(wr + 8);    // even ks, b1
        float2 o0 = *(const float2*)(wr + 16);   // odd  ks, b0
        float2 o1 = *(const float2*)(wr + 24);   // odd  ks, b1
        uint4 o;
        o.x = pack_h2(fmaxf(e0.x, 0.f), fmaxf(e0.y, 0.f));
        o.y = pack_h2(fmaxf(e1.x, 0.f), fmaxf(e1.y, 0.f));
        o.z = pack_h2(fmaxf(o0.x, 0.f), fmaxf(o0.y, 0.f));
        o.w = pack_h2(fmaxf(o1.x, 0.f), fmaxf(o1.y, 0.f));
        g_wfrag2[j] = o;
    }
}

// f16-accumulator HMMA: D(f16x2 x2) += A * B
__device__ __forceinline__ void mma_f16(uint32_t acc[2], const uint4& a,
                                        uint32_t b0, uint32_t b1) {
    asm volatile(
        "mma.sync.aligned.m16n8k16.row.col.f16.f16.f16.f16 "
        "{%0,%1}, {%2,%3,%4,%5}, {%6,%7}, {%0,%1};"
        : "+r"(acc[0]), "+r"(acc[1])
        : "r"(a.x), "r"(a.y), "r"(a.z), "r"(a.w), "r"(b0), "r"(b1));
}

// ---------------- main fused kernel ----------------
// CTA: 128 threads / 4 warps. Warp tile M=16 x N=32 (4 n8-tiles share a-frags,
// f16 accumulators: 2 regs per n8-tile per branch = 64 acc regs total).
// CTA tile: M=16 x N=128. grid = (8192/128, 1024/16) = (64, 64)
__global__ __launch_bounds__(128, 4)
void dendrite_main(const float* __restrict__ g_syn,
                   const float* __restrict__ plateaus,
                   const float* __restrict__ g_e,
                   const float* __restrict__ v_mem,
                   float* __restrict__ out)
{
    const float SYN_DECAY     = 0.99335550625f;  // exp(-0.1/15)
    const float PLATEAU_DECAY = 0.99875078085f;  // exp(-0.1/80)
    const float E_DECAY       = 0.98019867331f;  // exp(-0.1/5)

    const int tid = threadIdx.x;
    const int w = tid >> 5, lane = tid & 31;
    const int mt = blockIdx.y;
    const int bx = blockIdx.x;
    const int b0 = mt * 16, n0 = bx * 128;

    const uint4* xf = g_xfrag  + (size_t)mt * 1024 + lane;
    const uint4* wf = g_wfrag2 + (size_t)(bx * 16 + w * 4) * 512 + lane;

    uint32_t acc[NB][4][2];
    #pragma unroll
    for (int k = 0; k < NB; k++)
        #pragma unroll
        for (int nt = 0; nt < 4; nt++) { acc[k][nt][0] = 0u; acc[k][nt][1] = 0u; }

    #pragma unroll
    for (int t = 0; t < 16; t++) {
        uint4 a0 = xf[(2 * t) * 32];
        uint4 a1 = xf[(2 * t + 1) * 32];
        const int k = t >> 1;
        #pragma unroll
        for (int nt = 0; nt < 4; nt++) {
            uint4 bb = wf[nt * 512 + t * 32];
            mma_f16(acc[k][nt], a0, bb.x, bb.y);
            mma_f16(acc[k][nt], a1, bb.z, bb.w);
        }
    }

    // ---- fused elementwise epilogue ----
    const int g = lane >> 2, q = lane & 3;

    #pragma unroll
    for (int nt = 0; nt < 4; nt++) {
        const int n = n0 + (w * 4 + nt) * 8 + 2 * q;   // this thread's 2 neuron cols
        #pragma unroll
        for (int h = 0; h < 2; h++) {
            const int b = b0 + g + h * 8;
            const size_t base = (size_t)b * NN + n;

            // unpack this (nt, row-half)'s accumulators: 8 branches x (col, col+1)
            float2 dv[NB];
            #pragma unroll
            for (int k = 0; k < NB; k++)
                dv[k] = __half22float2(*(const __half2*)&acc[k][nt][h]);

            const float4* gp = (const float4*)(g_syn + base * NB);
            const float4* pp = (const float4*)(plateaus + base * NB);
            float4 gsA = gp[0], gsB = gp[1], gsC = gp[2], gsD = gp[3];
            float4 plA = pp[0], plB = pp[1], plC = pp[2], plD = pp[3];
            float2 ge2 = *(const float2*)(g_e + base);
            float2 vm2 = *(const float2*)(v_mem + base);

            float gs[2][8] = {{gsA.x, gsA.y, gsA.z, gsA.w, gsB.x, gsB.y, gsB.z, gsB.w},
                              {gsC.x, gsC.y, gsC.z, gsC.w, gsD.x, gsD.y, gsD.z, gsD.w}};
            float pl[2][8] = {{plA.x, plA.y, plA.z, plA.w, plB.x, plB.y, plB.z, plB.w},
                              {plC.x, plC.y, plC.z, plC.w, plD.x, plD.y, plD.z, plD.w}};
            float gev[2] = {ge2.x, ge2.y};
            float vmv[2] = {vm2.x, vm2.y};
            float spk[2], vo[2];

            #pragma unroll
            for (int j = 0; j < 2; j++) {
                float soma = 0.f;
                #pragma unroll
                for (int k = 0; k < NB; k++) {
                    const float av = j ? dv[k].y : dv[k].x;
                    const float gv = fmaf(SYN_DECAY, gs[j][k], av);
                    const bool supra = gv > 0.3f;
                    const float nmda = gv * (supra ? 3.0f : 0.8f);
                    float pv = PLATEAU_DECAY * pl[j][k];
                    if (supra) pv = fmaxf(pv, nmda);
                    // 2*tanh(t/2) = 2*(1-e^-t)/(1+e^-t)
                    const float e = __expf(-(nmda + pv));
                    soma += 2.0f * __fdividef(1.0f - e, 1.0f + e);
                }
                const float ge_n = fmaf(E_DECAY, gev[j], soma);
                float v = vmv[j] + 0.005f * (ge_n * (3.0f - vmv[j]) - vmv[j]);
                spk[j] = (v >= 1.0f) ? 1.0f : 0.0f;
                vo[j]  = (v >= 1.0f) ? 0.0f : v;
            }
            *(float2*)(out + base) = make_float2(spk[0], spk[1]);
            *(float2*)(out + (size_t)BATCH * NN + base) = make_float2(vo[0], vo[1]);
        }
    }
}

extern "C" void kernel_launch(void* const* d_in, const int* in_sizes, int n_in,
                              void* d_out, int out_size) {
    const float* inputs   = (const float*)d_in[0];
    const float* bw       = (const float*)d_in[1];
    const float* g_syn    = (const float*)d_in[2];
    const float* plateaus = (const float*)d_in[3];
    const float* g_e      = (const float*)d_in[4];
    const float* v_mem    = (const float*)d_in[5];
    float* out = (float*)d_out;

    const int NTOT = 64 * 32 * 32 + 1024 * 16 * 32;
    prep_kernel<<<(NTOT + 255) / 256, 256>>>(inputs, bw);

    dim3 grid(NN / 128, BATCH / 16);   // (64, 64) = 4096 CTAs of 128 threads
    dendrite_main<<<grid, 128>>>(g_syn, plateaus, g_e, v_mem, out);
}